// round 15
// baseline (speedup 1.0000x reference)
#include <cuda_runtime.h>
#include <cuda_bf16.h>
#include <cuda_fp16.h>
#include <stdint.h>

#define NN 100000
#define EE 1600000
#define FIN 128
#define HH 32
#define CC 16
#define GG 64
#define CAP 96        // fixed CSR row capacity
#define FULLM 0xffffffffu
#define AMXB 3125     // argmax role-blocks (32 nodes each: 8 warps x 4 nodes)
#define EDGEB 6250    // build role-blocks (256 edges each)

// ---------------- static device scratch (zero-init; layer2 last block re-zeroes) ----------------
__device__ unsigned char g_vidx[NN];
__device__ int   g_deg[NN + 24];
__device__ unsigned int g_csr[NN * CAP];   // plain src indices
__device__ __half g_etabh[128 * HH];       // embW1 fp16 (64B rows)
__device__ float g_stab[128];
__device__ float g_dtab[128];
__device__ __half g_h2lin[NN * CC];        // layer-2 linear feats fp16 (32B rows)
__device__ float g_a2s[NN];
__device__ float g_a2d[NN];
__device__ float g_pool[GG * CC];
__device__ int   g_done;

__device__ __forceinline__ __half2 splat_h(unsigned bits16) {
    unsigned sp = bits16 * 0x10001u;
    return *reinterpret_cast<__half2*>(&sp);
}

__device__ __forceinline__ int lbound(const int* a, int n, int v) {
    int lo = 0, hi = n;
    while (lo < hi) { int m = (lo + hi) >> 1; if (a[m] < v) lo = m + 1; else hi = m; }
    return lo;
}

__device__ __forceinline__ int warp_argmax128(float4 v, int lane) {
    float bv = v.x; int bi = lane * 4;
    if (v.y > bv) { bv = v.y; bi = lane * 4 + 1; }
    if (v.z > bv) { bv = v.z; bi = lane * 4 + 2; }
    if (v.w > bv) { bv = v.w; bi = lane * 4 + 3; }
#pragma unroll
    for (int off = 16; off; off >>= 1) {
        float ov = __shfl_xor_sync(FULLM, bv, off);
        int   oi = __shfl_xor_sync(FULLM, bi, off);
        if (ov > bv || (ov == bv && oi < bi)) { bv = ov; bi = oi; }
    }
    return bi;
}

// ========== launch 1: fused argmax | vocab tables | CSR build (interleaved, reg-capped) ==========
__global__ __launch_bounds__(256, 6) void k_fused(
        const float* __restrict__ x, const int* __restrict__ ei,
        const float* __restrict__ emb, const float* __restrict__ W1,
        const float* __restrict__ a1s, const float* __restrict__ a1d) {
    int b = blockIdx.x;
    if (b == 3 * AMXB) {
        // ---- vocab tables (1 block; spills OK) ----
        __shared__ float sW1[HH * HH];
        __shared__ float sas[HH], sad[HH];
        int t = threadIdx.x;
        for (int i = t; i < HH * HH; i += 256) sW1[i] = W1[i];
        if (t < HH) { sas[t] = a1s[t]; sad[t] = a1d[t]; }
        __syncthreads();
        if (t >= 128) return;
        float e[HH];
#pragma unroll
        for (int j = 0; j < HH; j++) e[j] = emb[t * HH + j];
        float ss = 0.f, dd = 0.f;
#pragma unroll 4
        for (int k = 0; k < HH; k++) {
            float sum = 0.f;
#pragma unroll
            for (int j = 0; j < HH; j++) sum += e[j] * sW1[j * HH + k];
            g_etabh[t * HH + k] = __float2half(sum);
            ss += sum * sas[k];
            dd += sum * sad[k];
        }
        g_stab[t] = ss;
        g_dtab[t] = dd;
        return;
    }
    int r = b % 3, q = b / 3;
    if (r == 0) {
        // ---- argmax: warp handles 4 consecutive nodes, all loads issued up front ----
        int w = threadIdx.x >> 5;
        int lane = threadIdx.x & 31;
        int n0 = (q * 8 + w) * 4;
        const float4* rows = (const float4*)(x + (size_t)n0 * FIN);
        float4 v0 = rows[lane];
        float4 v1 = rows[32 + lane];
        float4 v2 = rows[64 + lane];
        float4 v3 = rows[96 + lane];
        int b0 = warp_argmax128(v0, lane);
        int b1 = warp_argmax128(v1, lane);
        int b2 = warp_argmax128(v2, lane);
        int b3 = warp_argmax128(v3, lane);
        if (!lane)
            *(uchar4*)&g_vidx[n0] = make_uchar4((unsigned char)b0, (unsigned char)b1,
                                                (unsigned char)b2, (unsigned char)b3);
    } else {
        // ---- CSR build (no vidx dependency) ----
        int e = (q * 2 + (r - 1)) * 256 + threadIdx.x;
        if (e >= EE) return;
        int s = ei[e];
        int d = ei[EE + e];
        int t = atomicAdd(&g_deg[d], 1);
        if (t < CAP) g_csr[d * CAP + t] = (unsigned)s;
    }
}

// ===== launch 2: layer 1 — 2 nodes/warp, packed single-shfl consume, HFMA2 accum =====
__global__ __launch_bounds__(256) void k_layer1(
        const float* __restrict__ b1, const float* __restrict__ W2,
        const float* __restrict__ a2src, const float* __restrict__ a2dst) {
    __shared__ float s_s[128], s_d[128];
    __shared__ float s_b1[HH];
    __shared__ float s_W2[HH * CC];
    __shared__ float s_a2s[CC], s_a2d[CC];
    __shared__ float s_h1[16][HH];

    int tid = threadIdx.x;
    if (tid < 128) { s_s[tid] = g_stab[tid]; s_d[tid] = g_dtab[tid]; }
    s_W2[tid] = W2[tid];
    s_W2[tid + 256] = W2[tid + 256];
    if (tid < HH) s_b1[tid] = b1[tid];
    if (tid < CC) { s_a2s[tid] = a2src[tid]; s_a2d[tid] = a2dst[tid]; }
    __syncthreads();

    int w = tid >> 5;
    int lane = tid & 31;
    int h   = lane >> 4;
    int s16 = lane & 15;
    int sub  = s16 & 7;        // uint2 chunk (4 halves) of the 32-dim row
    int slot = s16 >> 3;       // edge slot (2 per half)
    int hbase = h << 4;

    int i = blockIdx.x * 16 + w * 2 + h;

    const uint2* etab = (const uint2*)g_etabh;

    int vi = g_vidx[i];
    float ad = s_d[vi];
    float es = s_s[vi] + ad;
    es = es > 0.f ? es : 0.2f * es;
    float exs = __expf(es);

    int deg = min(g_deg[i], CAP);
    int dmax = max(deg, __shfl_xor_sync(FULLM, deg, 16));  // warp-uniform
    int base = i * CAP;
    float dloc = 0.f;

    __half2 acch0 = __floats2half2_rn(0.f, 0.f);
    __half2 acch1 = acch0;

    if (dmax <= 32) {
        unsigned pk0 = 0, pk1 = 0;
        bool v0 = s16 < deg, v1 = s16 + 16 < deg;
        unsigned p0 = v0 ? g_csr[base + s16] : 0;
        unsigned p1 = v1 ? g_csr[base + s16 + 16] : 0;
        unsigned w0 = v0 ? g_vidx[p0] : 0;
        unsigned w1 = v1 ? g_vidx[p1] : 0;
        if (v0) {
            float e = s_s[w0] + ad;
            e = e > 0.f ? e : 0.2f * e;
            float ex = __expf(e); dloc += ex;
            pk0 = (w0 << 16) | (unsigned)__half_as_ushort(__float2half(ex));
        }
        if (v1) {
            float e = s_s[w1] + ad;
            e = e > 0.f ? e : 0.2f * e;
            float ex = __expf(e); dloc += ex;
            pk1 = (w1 << 16) | (unsigned)__half_as_ushort(__float2half(ex));
        }
        int steps0 = (min(dmax, 16) + 1) >> 1;
        int steps1 = dmax > 16 ? ((dmax - 16 + 1) >> 1) : 0;
#pragma unroll
        for (int st = 0; st < 8; st++) {
            if (st >= steps0) break;
            unsigned pk = __shfl_sync(FULLM, pk0, hbase + (st << 1) + slot);
            uint2 u = __ldg(&etab[(pk >> 16) * 8 + sub]);
            __half2 wh = splat_h(pk & 0xFFFFu);
            acch0 = __hfma2(wh, *(__half2*)&u.x, acch0);
            acch1 = __hfma2(wh, *(__half2*)&u.y, acch1);
        }
#pragma unroll
        for (int st = 0; st < 8; st++) {
            if (st >= steps1) break;
            unsigned pk = __shfl_sync(FULLM, pk1, hbase + (st << 1) + slot);
            uint2 u = __ldg(&etab[(pk >> 16) * 8 + sub]);
            __half2 wh = splat_h(pk & 0xFFFFu);
            acch0 = __hfma2(wh, *(__half2*)&u.x, acch0);
            acch1 = __hfma2(wh, *(__half2*)&u.y, acch1);
        }
    } else {
        for (int b0 = 0; b0 < dmax; b0 += 16) {
            int rel = b0 + s16;
            unsigned pk = 0;
            if (rel < deg) {
                unsigned p = g_csr[base + rel];
                unsigned v = g_vidx[p];
                float e = s_s[v] + ad;
                e = e > 0.f ? e : 0.2f * e;
                float ex = __expf(e); dloc += ex;
                pk = (v << 16) | (unsigned)__half_as_ushort(__float2half(ex));
            }
            int steps = (min(dmax - b0, 16) + 1) >> 1;
#pragma unroll
            for (int st = 0; st < 8; st++) {
                if (st >= steps) break;
                unsigned pb = __shfl_sync(FULLM, pk, hbase + (st << 1) + slot);
                uint2 u = __ldg(&etab[(pb >> 16) * 8 + sub]);
                __half2 wh = splat_h(pb & 0xFFFFu);
                acch0 = __hfma2(wh, *(__half2*)&u.x, acch0);
                acch1 = __hfma2(wh, *(__half2*)&u.y, acch1);
            }
        }
    }

    float2 f0 = __half22float2(acch0);
    float2 f1 = __half22float2(acch1);
    float4 acc = make_float4(f0.x, f0.y, f1.x, f1.y);
    if (slot == 0) {
        uint2 u = __ldg(&etab[vi * 8 + sub]);
        __half2 h0 = *(__half2*)&u.x, h1 = *(__half2*)&u.y;
        float2 r0 = __half22float2(h0), r1 = __half22float2(h1);
        acc.x += exs * r0.x; acc.y += exs * r0.y;
        acc.z += exs * r1.x; acc.w += exs * r1.y;
    }

    float den = dloc;
#pragma unroll
    for (int off = 8; off; off >>= 1) den += __shfl_xor_sync(FULLM, den, off);
    den += exs;

    acc.x += __shfl_xor_sync(FULLM, acc.x, 8);
    acc.y += __shfl_xor_sync(FULLM, acc.y, 8);
    acc.z += __shfl_xor_sync(FULLM, acc.z, 8);
    acc.w += __shfl_xor_sync(FULLM, acc.w, 8);

    float inv = 1.0f / (den + 1e-16f);
    int nrow = w * 2 + h;
    if (slot == 0) {
        float4 hh;
        hh.x = fmaxf(acc.x * inv + s_b1[sub * 4 + 0], 0.f);
        hh.y = fmaxf(acc.y * inv + s_b1[sub * 4 + 1], 0.f);
        hh.z = fmaxf(acc.z * inv + s_b1[sub * 4 + 2], 0.f);
        hh.w = fmaxf(acc.w * inv + s_b1[sub * 4 + 3], 0.f);
        ((float4*)s_h1[nrow])[sub] = hh;
    }
    __syncwarp();

    // layer-2 linear: each lane owns channel s16 of its node
    float sum = 0.f;
#pragma unroll
    for (int k = 0; k < HH; k++) sum += s_h1[nrow][k] * s_W2[k * CC + s16];
    float nb = __shfl_sync(FULLM, sum, (lane + 1) & 31);
    if (!(s16 & 1))
        ((__half2*)g_h2lin)[i * 8 + (s16 >> 1)] = __floats2half2_rn(sum, nb);
    float ps = sum * s_a2s[s16];
    float pd = sum * s_a2d[s16];
#pragma unroll
    for (int off = 8; off; off >>= 1) {
        ps += __shfl_xor_sync(FULLM, ps, off);
        pd += __shfl_xor_sync(FULLM, pd, off);
    }
    if (!s16) { g_a2s[i] = ps; g_a2d[i] = pd; }
}

// ===== launch 3: layer 2 + fused block pooling + last-block softmax/cleanup =====
__global__ __launch_bounds__(256) void k_layer2(const int* __restrict__ batch,
                                                const float* __restrict__ b2,
                                                float* __restrict__ out) {
    __shared__ float s_b2[CC];
    __shared__ float s_pool[4][CC];
    __shared__ int s_gfirst, s_gspan;
    __shared__ int s_last;

    int tid = threadIdx.x;
    if (tid < CC) s_b2[tid] = b2[tid];
    if (tid < 64) s_pool[tid >> 4][tid & 15] = 0.f;
    if (tid == 0) {
        int gf = batch[blockIdx.x * 16];
        s_gfirst = gf;
        s_gspan = batch[blockIdx.x * 16 + 15] - gf;
    }
    __syncthreads();

    int w = tid >> 5;
    int lane = tid & 31;
    int h   = lane >> 4;
    int s16 = lane & 15;
    int sub  = s16 & 3;        // uint2 chunk (4 halves) of the 16-dim row
    int slot = s16 >> 2;       // edge slot (4 per half)
    int hbase = h << 4;

    int i = blockIdx.x * 16 + w * 2 + h;

    const uint2* hl = (const uint2*)g_h2lin;

    float ad = g_a2d[i];
    float es = g_a2s[i] + ad;
    es = es > 0.f ? es : 0.2f * es;
    float exs = __expf(es);

    int deg = min(g_deg[i], CAP);
    int dmax = max(deg, __shfl_xor_sync(FULLM, deg, 16));
    int base = i * CAP;
    float dloc = 0.f;

    __half2 acch0 = __floats2half2_rn(0.f, 0.f);
    __half2 acch1 = acch0;

    if (dmax <= 32) {
        unsigned pk0 = 0, pk1 = 0;
        bool v0 = s16 < deg, v1 = s16 + 16 < deg;
        unsigned p0 = v0 ? g_csr[base + s16] : 0;
        unsigned p1 = v1 ? g_csr[base + s16 + 16] : 0;
        float as0 = v0 ? g_a2s[p0] : 0.f;
        float as1 = v1 ? g_a2s[p1] : 0.f;
        if (v0) {
            float e = as0 + ad;
            e = e > 0.f ? e : 0.2f * e;
            float ex = __expf(e); dloc += ex;
            pk0 = (p0 << 15) | (unsigned)__half_as_ushort(__float2half(ex));  // ex>0: sign bit 0
        }
        if (v1) {
            float e = as1 + ad;
            e = e > 0.f ? e : 0.2f * e;
            float ex = __expf(e); dloc += ex;
            pk1 = (p1 << 15) | (unsigned)__half_as_ushort(__float2half(ex));
        }
        int steps0 = (min(dmax, 16) + 3) >> 2;
        int steps1 = dmax > 16 ? ((dmax - 16 + 3) >> 2) : 0;
#pragma unroll
        for (int st = 0; st < 4; st++) {
            if (st >= steps0) break;
            unsigned pk = __shfl_sync(FULLM, pk0, hbase + (st << 2) + slot);
            uint2 u = __ldg(&hl[(pk >> 15) * 4 + sub]);
            __half2 wh = splat_h(pk & 0x7FFFu);
            acch0 = __hfma2(wh, *(__half2*)&u.x, acch0);
            acch1 = __hfma2(wh, *(__half2*)&u.y, acch1);
        }
#pragma unroll
        for (int st = 0; st < 4; st++) {
            if (st >= steps1) break;
            unsigned pk = __shfl_sync(FULLM, pk1, hbase + (st << 2) + slot);
            uint2 u = __ldg(&hl[(pk >> 15) * 4 + sub]);
            __half2 wh = splat_h(pk & 0x7FFFu);
            acch0 = __hfma2(wh, *(__half2*)&u.x, acch0);
            acch1 = __hfma2(wh, *(__half2*)&u.y, acch1);
        }
    } else {
        for (int b0 = 0; b0 < dmax; b0 += 16) {
            int rel = b0 + s16;
            unsigned pk = 0;
            if (rel < deg) {
                unsigned p = g_csr[base + rel];
                float e = g_a2s[p] + ad;
                e = e > 0.f ? e : 0.2f * e;
                float ex = __expf(e); dloc += ex;
                pk = (p << 15) | (unsigned)__half_as_ushort(__float2half(ex));
            }
            int steps = (min(dmax - b0, 16) + 3) >> 2;
#pragma unroll
            for (int st = 0; st < 4; st++) {
                if (st >= steps) break;
                unsigned pb = __shfl_sync(FULLM, pk, hbase + (st << 2) + slot);
                uint2 u = __ldg(&hl[(pb >> 15) * 4 + sub]);
                __half2 wh = splat_h(pb & 0x7FFFu);
                acch0 = __hfma2(wh, *(__half2*)&u.x, acch0);
                acch1 = __hfma2(wh, *(__half2*)&u.y, acch1);
            }
        }
    }

    float2 f0 = __half22float2(acch0);
    float2 f1 = __half22float2(acch1);
    float4 acc = make_float4(f0.x, f0.y, f1.x, f1.y);
    if (slot == 0) {
        uint2 u = __ldg(&hl[i * 4 + sub]);
        __half2 h0 = *(__half2*)&u.x, h1 = *(__half2*)&u.y;
        float2 r0 = __half22float2(h0), r1 = __half22float2(h1);
        acc.x += exs * r0.x; acc.y += exs * r0.y;
        acc.z += exs * r1.x; acc.w += exs * r1.y;
    }

    float den = dloc;
#pragma unroll
    for (int off = 8; off; off >>= 1) den += __shfl_xor_sync(FULLM, den, off);
    den += exs;

#pragma unroll
    for (int off = 4; off <= 8; off <<= 1) {
        acc.x += __shfl_xor_sync(FULLM, acc.x, off);
        acc.y += __shfl_xor_sync(FULLM, acc.y, off);
        acc.z += __shfl_xor_sync(FULLM, acc.z, off);
        acc.w += __shfl_xor_sync(FULLM, acc.w, off);
    }

    float inv = 1.0f / (den + 1e-16f);
    if (slot == 0) {
        float hx = acc.x * inv + s_b2[sub * 4 + 0];
        float hy = acc.y * inv + s_b2[sub * 4 + 1];
        float hz = acc.z * inv + s_b2[sub * 4 + 2];
        float hw = acc.w * inv + s_b2[sub * 4 + 3];
        int g = batch[i];
        int r = g - s_gfirst;
        if (r < 4) {
            atomicAdd(&s_pool[r][sub * 4 + 0], hx);
            atomicAdd(&s_pool[r][sub * 4 + 1], hy);
            atomicAdd(&s_pool[r][sub * 4 + 2], hz);
            atomicAdd(&s_pool[r][sub * 4 + 3], hw);
        } else {   // pathological span — direct global (essentially never)
            atomicAdd(&g_pool[g * CC + sub * 4 + 0], hx);
            atomicAdd(&g_pool[g * CC + sub * 4 + 1], hy);
            atomicAdd(&g_pool[g * CC + sub * 4 + 2], hz);
            atomicAdd(&g_pool[g * CC + sub * 4 + 3], hw);
        }
    }
    __syncthreads();

    // flush block pool to global
    if (tid < 64) {
        int r = tid >> 4, ch = tid & 15;
        if (r <= s_gspan && r < 4)
            atomicAdd(&g_pool[(s_gfirst + r) * CC + ch], s_pool[r][ch]);
    }
    __threadfence();
    if (tid == 0) s_last = (atomicAdd(&g_done, 1) == (int)gridDim.x - 1);
    __syncthreads();

    if (s_last) {
        __threadfence();
        // counts + softmax, thread per graph
        if (tid < GG) {
            int lo = lbound(batch, NN, tid);
            int hi = lbound(batch, NN, tid + 1);
            float cden = fmaxf((float)(hi - lo), 1.0f);
            float v[CC];
            float mx = -1e30f;
#pragma unroll
            for (int j = 0; j < CC; j++) { v[j] = g_pool[tid * CC + j] / cden; mx = fmaxf(mx, v[j]); }
            float ssum = 0.f;
#pragma unroll
            for (int j = 0; j < CC; j++) { v[j] = __expf(v[j] - mx); ssum += v[j]; }
            float invs = 1.0f / ssum;
#pragma unroll
            for (int j = 0; j < CC; j++) out[tid * CC + j] = v[j] * invs;
        }
        __syncthreads();
        // cleanup for next replay
        for (int idx = tid; idx < GG * CC; idx += 256) g_pool[idx] = 0.f;
        for (int i4 = tid; i4 * 4 < NN; i4 += 256)
            ((int4*)g_deg)[i4] = make_int4(0, 0, 0, 0);
        if (tid == 0) g_done = 0;
    }
}

// ---------------- launch ----------------
extern "C" void kernel_launch(void* const* d_in, const int* in_sizes, int n_in,
                              void* d_out, int out_size) {
    const float* x      = (const float*)d_in[0];
    const int*   ei     = (const int*)d_in[1];
    const int*   batch  = (const int*)d_in[2];
    const float* emb    = (const float*)d_in[3];
    const float* W1     = (const float*)d_in[4];
    const float* a1s    = (const float*)d_in[5];
    const float* a1d    = (const float*)d_in[6];
    const float* b1     = (const float*)d_in[7];
    const float* W2     = (const float*)d_in[8];
    const float* a2s    = (const float*)d_in[9];
    const float* a2d    = (const float*)d_in[10];
    const float* b2     = (const float*)d_in[11];
    float* out = (float*)d_out;

    const int node16Blocks = NN / 16;                 // 6250

    k_fused<<<3 * AMXB + 1, 256>>>(x, ei, emb, W1, a1s, a1d);
    k_layer1<<<node16Blocks, 256>>>(b1, W2, a2s, a2d);
    k_layer2<<<node16Blocks, 256>>>(batch, b2, out);
    (void)in_sizes; (void)n_in; (void)out_size;
}

// round 16
// speedup vs baseline: 1.1864x; 1.1864x over previous
#include <cuda_runtime.h>
#include <cuda_bf16.h>
#include <cuda_fp16.h>
#include <stdint.h>

#define NN 100000
#define EE 1600000
#define FIN 128
#define HH 32
#define CC 16
#define GG 64
#define CAP 96        // fixed CSR row capacity
#define FULLM 0xffffffffu
#define AMXB 3125     // argmax role-blocks (32 nodes each: 8 warps x 4 nodes)
#define EDGEB 6250    // build role-blocks (256 edges each)
#define ZEROB 98

// ---------------- static device scratch ----------------
__device__ unsigned char g_vidx[NN];
__device__ int   g_deg[NN + 24];
__device__ unsigned int g_csr[NN * CAP];   // plain src indices
__device__ __half g_etabh[128 * HH];       // embW1 fp16 (64B rows)
__device__ float g_stab[128];
__device__ float g_dtab[128];
__device__ __half g_h2lin[NN * CC];        // layer-2 linear feats fp16 (32B rows)
__device__ float g_h2out[NN * CC];
__device__ float g_a2s[NN];
__device__ float g_a2d[NN];

__device__ __forceinline__ __half2 splat_h(unsigned bits16) {
    unsigned sp = bits16 * 0x10001u;
    return *reinterpret_cast<__half2*>(&sp);
}

// ================= launch 1: zero degree counters =================
__global__ void k_zero() {
    int i4 = blockIdx.x * 256 + threadIdx.x;
    if (i4 * 4 < NN) ((int4*)g_deg)[i4] = make_int4(0, 0, 0, 0);
}

// REDUX-based warp argmax over 128 floats (exact lowest-index tiebreak)
__device__ __forceinline__ int warp_argmax128(float4 v, int lane) {
    float bv = v.x; int loc = 0;
    if (v.y > bv) { bv = v.y; loc = 1; }
    if (v.z > bv) { bv = v.z; loc = 2; }
    if (v.w > bv) { bv = v.w; loc = 3; }
    unsigned b = __float_as_uint(bv);
    unsigned key = (b & 0x80000000u) ? ~b : (b | 0x80000000u);  // order-preserving
    unsigned mx = __reduce_max_sync(FULLM, key);
    unsigned ball = __ballot_sync(FULLM, key == mx);
    int winlane = __ffs(ball) - 1;          // lowest lane = lowest index range
    int wloc = __shfl_sync(FULLM, loc, winlane);
    return winlane * 4 + wloc;
}

// ========== launch 2: fused argmax | vocab tables | CSR build (interleaved, reg-capped) ==========
__global__ __launch_bounds__(256, 8) void k_fused(
        const float* __restrict__ x, const int* __restrict__ ei,
        const float* __restrict__ emb, const float* __restrict__ W1,
        const float* __restrict__ a1s, const float* __restrict__ a1d) {
    int b = blockIdx.x;
    if (b == 3 * AMXB) {
        // ---- vocab tables (1 block; spills OK) ----
        __shared__ float sW1[HH * HH];
        __shared__ float sas[HH], sad[HH];
        int t = threadIdx.x;
        for (int i = t; i < HH * HH; i += 256) sW1[i] = W1[i];
        if (t < HH) { sas[t] = a1s[t]; sad[t] = a1d[t]; }
        __syncthreads();
        if (t >= 128) return;
        float e[HH];
#pragma unroll
        for (int j = 0; j < HH; j++) e[j] = emb[t * HH + j];
        float ss = 0.f, dd = 0.f;
#pragma unroll 4
        for (int k = 0; k < HH; k++) {
            float sum = 0.f;
#pragma unroll
            for (int j = 0; j < HH; j++) sum += e[j] * sW1[j * HH + k];
            g_etabh[t * HH + k] = __float2half(sum);
            ss += sum * sas[k];
            dd += sum * sad[k];
        }
        g_stab[t] = ss;
        g_dtab[t] = dd;
        return;
    }
    int r = b % 3, q = b / 3;
    if (r == 0) {
        // ---- argmax: warp handles 4 consecutive nodes, all loads issued up front ----
        int w = threadIdx.x >> 5;
        int lane = threadIdx.x & 31;
        int n0 = (q * 8 + w) * 4;
        const float4* rows = (const float4*)(x + (size_t)n0 * FIN);
        float4 v0 = rows[lane];
        float4 v1 = rows[32 + lane];
        float4 v2 = rows[64 + lane];
        float4 v3 = rows[96 + lane];
        int b0 = warp_argmax128(v0, lane);
        int b1 = warp_argmax128(v1, lane);
        int b2 = warp_argmax128(v2, lane);
        int b3 = warp_argmax128(v3, lane);
        if (!lane)
            *(uchar4*)&g_vidx[n0] = make_uchar4((unsigned char)b0, (unsigned char)b1,
                                                (unsigned char)b2, (unsigned char)b3);
    } else {
        // ---- CSR build (no vidx dependency) ----
        int e = (q * 2 + (r - 1)) * 256 + threadIdx.x;
        if (e >= EE) return;
        int s = ei[e];
        int d = ei[EE + e];
        int t = atomicAdd(&g_deg[d], 1);
        if (t < CAP) g_csr[d * CAP + t] = (unsigned)s;
    }
}

// ===== launch 3: layer 1 — 2 nodes/warp, packed single-shfl consume, HFMA2 accum =====
__global__ __launch_bounds__(256) void k_layer1(
        const float* __restrict__ b1, const float* __restrict__ W2,
        const float* __restrict__ a2src, const float* __restrict__ a2dst) {
    __shared__ float s_s[128], s_d[128];
    __shared__ float s_b1[HH];
    __shared__ float s_W2[HH * CC];
    __shared__ float s_a2s[CC], s_a2d[CC];
    __shared__ float s_h1[16][HH];

    int tid = threadIdx.x;
    if (tid < 128) { s_s[tid] = g_stab[tid]; s_d[tid] = g_dtab[tid]; }
    s_W2[tid] = W2[tid];
    s_W2[tid + 256] = W2[tid + 256];
    if (tid < HH) s_b1[tid] = b1[tid];
    if (tid < CC) { s_a2s[tid] = a2src[tid]; s_a2d[tid] = a2dst[tid]; }
    __syncthreads();

    int w = tid >> 5;
    int lane = tid & 31;
    int h   = lane >> 4;
    int s16 = lane & 15;
    int sub  = s16 & 7;        // uint2 chunk (4 halves) of the 32-dim row
    int slot = s16 >> 3;       // edge slot (2 per half)
    int hbase = h << 4;

    int i = blockIdx.x * 16 + w * 2 + h;

    const uint2* etab = (const uint2*)g_etabh;

    int vi = g_vidx[i];
    float ad = s_d[vi];
    float es = s_s[vi] + ad;
    es = es > 0.f ? es : 0.2f * es;
    float exs = __expf(es);

    int deg = min(g_deg[i], CAP);
    int dmax = max(deg, __shfl_xor_sync(FULLM, deg, 16));  // warp-uniform
    int base = i * CAP;
    float dloc = 0.f;

    __half2 acch0 = __floats2half2_rn(0.f, 0.f);
    __half2 acch1 = acch0;

    if (dmax <= 32) {
        unsigned pk0 = 0, pk1 = 0;
        bool v0 = s16 < deg, v1 = s16 + 16 < deg;
        unsigned p0 = v0 ? g_csr[base + s16] : 0;
        unsigned p1 = v1 ? g_csr[base + s16 + 16] : 0;
        unsigned w0 = v0 ? g_vidx[p0] : 0;
        unsigned w1 = v1 ? g_vidx[p1] : 0;
        if (v0) {
            float e = s_s[w0] + ad;
            e = e > 0.f ? e : 0.2f * e;
            float ex = __expf(e); dloc += ex;
            pk0 = (w0 << 16) | (unsigned)__half_as_ushort(__float2half(ex));
        }
        if (v1) {
            float e = s_s[w1] + ad;
            e = e > 0.f ? e : 0.2f * e;
            float ex = __expf(e); dloc += ex;
            pk1 = (w1 << 16) | (unsigned)__half_as_ushort(__float2half(ex));
        }
        int steps0 = (min(dmax, 16) + 1) >> 1;
        int steps1 = dmax > 16 ? ((dmax - 16 + 1) >> 1) : 0;
#pragma unroll
        for (int st = 0; st < 8; st++) {
            if (st >= steps0) break;
            unsigned pk = __shfl_sync(FULLM, pk0, hbase + (st << 1) + slot);
            uint2 u = __ldg(&etab[(pk >> 16) * 8 + sub]);
            __half2 wh = splat_h(pk & 0xFFFFu);
            acch0 = __hfma2(wh, *(__half2*)&u.x, acch0);
            acch1 = __hfma2(wh, *(__half2*)&u.y, acch1);
        }
#pragma unroll
        for (int st = 0; st < 8; st++) {
            if (st >= steps1) break;
            unsigned pk = __shfl_sync(FULLM, pk1, hbase + (st << 1) + slot);
            uint2 u = __ldg(&etab[(pk >> 16) * 8 + sub]);
            __half2 wh = splat_h(pk & 0xFFFFu);
            acch0 = __hfma2(wh, *(__half2*)&u.x, acch0);
            acch1 = __hfma2(wh, *(__half2*)&u.y, acch1);
        }
    } else {
        for (int b0 = 0; b0 < dmax; b0 += 16) {
            int rel = b0 + s16;
            unsigned pk = 0;
            if (rel < deg) {
                unsigned p = g_csr[base + rel];
                unsigned v = g_vidx[p];
                float e = s_s[v] + ad;
                e = e > 0.f ? e : 0.2f * e;
                float ex = __expf(e); dloc += ex;
                pk = (v << 16) | (unsigned)__half_as_ushort(__float2half(ex));
            }
            int steps = (min(dmax - b0, 16) + 1) >> 1;
#pragma unroll
            for (int st = 0; st < 8; st++) {
                if (st >= steps) break;
                unsigned pb = __shfl_sync(FULLM, pk, hbase + (st << 1) + slot);
                uint2 u = __ldg(&etab[(pb >> 16) * 8 + sub]);
                __half2 wh = splat_h(pb & 0xFFFFu);
                acch0 = __hfma2(wh, *(__half2*)&u.x, acch0);
                acch1 = __hfma2(wh, *(__half2*)&u.y, acch1);
            }
        }
    }

    float2 f0 = __half22float2(acch0);
    float2 f1 = __half22float2(acch1);
    float4 acc = make_float4(f0.x, f0.y, f1.x, f1.y);
    if (slot == 0) {
        uint2 u = __ldg(&etab[vi * 8 + sub]);
        __half2 h0 = *(__half2*)&u.x, h1 = *(__half2*)&u.y;
        float2 r0 = __half22float2(h0), r1 = __half22float2(h1);
        acc.x += exs * r0.x; acc.y += exs * r0.y;
        acc.z += exs * r1.x; acc.w += exs * r1.y;
    }

    float den = dloc;
#pragma unroll
    for (int off = 8; off; off >>= 1) den += __shfl_xor_sync(FULLM, den, off);
    den += exs;

    acc.x += __shfl_xor_sync(FULLM, acc.x, 8);
    acc.y += __shfl_xor_sync(FULLM, acc.y, 8);
    acc.z += __shfl_xor_sync(FULLM, acc.z, 8);
    acc.w += __shfl_xor_sync(FULLM, acc.w, 8);

    float inv = 1.0f / (den + 1e-16f);
    int nrow = w * 2 + h;
    if (slot == 0) {
        float4 hh;
        hh.x = fmaxf(acc.x * inv + s_b1[sub * 4 + 0], 0.f);
        hh.y = fmaxf(acc.y * inv + s_b1[sub * 4 + 1], 0.f);
        hh.z = fmaxf(acc.z * inv + s_b1[sub * 4 + 2], 0.f);
        hh.w = fmaxf(acc.w * inv + s_b1[sub * 4 + 3], 0.f);
        ((float4*)s_h1[nrow])[sub] = hh;
    }
    __syncwarp();

    // layer-2 linear: each lane owns channel s16 of its node
    float sum = 0.f;
#pragma unroll
    for (int k = 0; k < HH; k++) sum += s_h1[nrow][k] * s_W2[k * CC + s16];
    float nb = __shfl_sync(FULLM, sum, (lane + 1) & 31);
    if (!(s16 & 1))
        ((__half2*)g_h2lin)[i * 8 + (s16 >> 1)] = __floats2half2_rn(sum, nb);
    float ps = sum * s_a2s[s16];
    float pd = sum * s_a2d[s16];
#pragma unroll
    for (int off = 8; off; off >>= 1) {
        ps += __shfl_xor_sync(FULLM, ps, off);
        pd += __shfl_xor_sync(FULLM, pd, off);
    }
    if (!s16) { g_a2s[i] = ps; g_a2d[i] = pd; }
}

// ===== launch 4: layer 2 — 2 nodes/warp, packed single-shfl consume, HFMA2 accum =====
__global__ __launch_bounds__(256) void k_layer2(const float* __restrict__ b2) {
    __shared__ float s_b2[CC];
    if (threadIdx.x < CC) s_b2[threadIdx.x] = b2[threadIdx.x];
    __syncthreads();

    int w = threadIdx.x >> 5;
    int lane = threadIdx.x & 31;
    int h   = lane >> 4;
    int s16 = lane & 15;
    int sub  = s16 & 3;        // uint2 chunk (4 halves) of the 16-dim row
    int slot = s16 >> 2;       // edge slot (4 per half)
    int hbase = h << 4;

    int i = blockIdx.x * 16 + w * 2 + h;

    const uint2* hl = (const uint2*)g_h2lin;

    float ad = g_a2d[i];
    float es = g_a2s[i] + ad;
    es = es > 0.f ? es : 0.2f * es;
    float exs = __expf(es);

    int deg = min(g_deg[i], CAP);
    int dmax = max(deg, __shfl_xor_sync(FULLM, deg, 16));
    int base = i * CAP;
    float dloc = 0.f;

    __half2 acch0 = __floats2half2_rn(0.f, 0.f);
    __half2 acch1 = acch0;

    if (dmax <= 32) {
        unsigned pk0 = 0, pk1 = 0;
        bool v0 = s16 < deg, v1 = s16 + 16 < deg;
        unsigned p0 = v0 ? g_csr[base + s16] : 0;
        unsigned p1 = v1 ? g_csr[base + s16 + 16] : 0;
        float as0 = v0 ? g_a2s[p0] : 0.f;
        float as1 = v1 ? g_a2s[p1] : 0.f;
        if (v0) {
            float e = as0 + ad;
            e = e > 0.f ? e : 0.2f * e;
            float ex = __expf(e); dloc += ex;
            pk0 = (p0 << 15) | (unsigned)__half_as_ushort(__float2half(ex));  // ex>0: sign bit 0
        }
        if (v1) {
            float e = as1 + ad;
            e = e > 0.f ? e : 0.2f * e;
            float ex = __expf(e); dloc += ex;
            pk1 = (p1 << 15) | (unsigned)__half_as_ushort(__float2half(ex));
        }
        int steps0 = (min(dmax, 16) + 3) >> 2;
        int steps1 = dmax > 16 ? ((dmax - 16 + 3) >> 2) : 0;
#pragma unroll
        for (int st = 0; st < 4; st++) {
            if (st >= steps0) break;
            unsigned pk = __shfl_sync(FULLM, pk0, hbase + (st << 2) + slot);
            uint2 u = __ldg(&hl[(pk >> 15) * 4 + sub]);
            __half2 wh = splat_h(pk & 0x7FFFu);
            acch0 = __hfma2(wh, *(__half2*)&u.x, acch0);
            acch1 = __hfma2(wh, *(__half2*)&u.y, acch1);
        }
#pragma unroll
        for (int st = 0; st < 4; st++) {
            if (st >= steps1) break;
            unsigned pk = __shfl_sync(FULLM, pk1, hbase + (st << 2) + slot);
            uint2 u = __ldg(&hl[(pk >> 15) * 4 + sub]);
            __half2 wh = splat_h(pk & 0x7FFFu);
            acch0 = __hfma2(wh, *(__half2*)&u.x, acch0);
            acch1 = __hfma2(wh, *(__half2*)&u.y, acch1);
        }
    } else {
        for (int b0 = 0; b0 < dmax; b0 += 16) {
            int rel = b0 + s16;
            unsigned pk = 0;
            if (rel < deg) {
                unsigned p = g_csr[base + rel];
                float e = g_a2s[p] + ad;
                e = e > 0.f ? e : 0.2f * e;
                float ex = __expf(e); dloc += ex;
                pk = (p << 15) | (unsigned)__half_as_ushort(__float2half(ex));
            }
            int steps = (min(dmax - b0, 16) + 3) >> 2;
#pragma unroll
            for (int st = 0; st < 4; st++) {
                if (st >= steps) break;
                unsigned pb = __shfl_sync(FULLM, pk, hbase + (st << 2) + slot);
                uint2 u = __ldg(&hl[(pb >> 15) * 4 + sub]);
                __half2 wh = splat_h(pb & 0x7FFFu);
                acch0 = __hfma2(wh, *(__half2*)&u.x, acch0);
                acch1 = __hfma2(wh, *(__half2*)&u.y, acch1);
            }
        }
    }

    float2 f0 = __half22float2(acch0);
    float2 f1 = __half22float2(acch1);
    float4 acc = make_float4(f0.x, f0.y, f1.x, f1.y);
    if (slot == 0) {
        uint2 u = __ldg(&hl[i * 4 + sub]);
        __half2 h0 = *(__half2*)&u.x, h1 = *(__half2*)&u.y;
        float2 r0 = __half22float2(h0), r1 = __half22float2(h1);
        acc.x += exs * r0.x; acc.y += exs * r0.y;
        acc.z += exs * r1.x; acc.w += exs * r1.y;
    }

    float den = dloc;
#pragma unroll
    for (int off = 8; off; off >>= 1) den += __shfl_xor_sync(FULLM, den, off);
    den += exs;

#pragma unroll
    for (int off = 4; off <= 8; off <<= 1) {
        acc.x += __shfl_xor_sync(FULLM, acc.x, off);
        acc.y += __shfl_xor_sync(FULLM, acc.y, off);
        acc.z += __shfl_xor_sync(FULLM, acc.z, off);
        acc.w += __shfl_xor_sync(FULLM, acc.w, off);
    }

    float inv = 1.0f / (den + 1e-16f);
    if (slot == 0) {
        float4 hh;
        hh.x = acc.x * inv + s_b2[sub * 4 + 0];
        hh.y = acc.y * inv + s_b2[sub * 4 + 1];
        hh.z = acc.z * inv + s_b2[sub * 4 + 2];
        hh.w = acc.w * inv + s_b2[sub * 4 + 3];
        ((float4*)g_h2out)[i * 4 + sub] = hh;
    }
}

// ===== launch 5: segmented mean-pool + softmax; block per graph =====
__device__ __forceinline__ int lbound(const int* a, int n, int v) {
    int lo = 0, hi = n;
    while (lo < hi) { int m = (lo + hi) >> 1; if (a[m] < v) lo = m + 1; else hi = m; }
    return lo;
}

__global__ void k_final(const int* __restrict__ batch, float* __restrict__ out) {
    __shared__ int s_lo, s_hi;
    __shared__ float4 s_acc[256];
    int g = blockIdx.x;
    if (threadIdx.x == 0) s_lo = lbound(batch, NN, g);
    if (threadIdx.x == 1) s_hi = lbound(batch, NN, g + 1);
    __syncthreads();
    int lo = s_lo, hi = s_hi;

    int nodelane = threadIdx.x >> 2;
    int sub = threadIdx.x & 3;
    float4 acc = make_float4(0.f, 0.f, 0.f, 0.f);
    const float4* ho = (const float4*)g_h2out;
    for (int n = lo + nodelane; n < hi; n += 64) {
        float4 v = ho[n * 4 + sub];
        acc.x += v.x; acc.y += v.y; acc.z += v.z; acc.w += v.w;
    }
    s_acc[threadIdx.x] = acc;
    __syncthreads();
    for (int off = 128; off >= 4; off >>= 1) {
        if (threadIdx.x < off) {
            float4 a = s_acc[threadIdx.x], b = s_acc[threadIdx.x + off];
            a.x += b.x; a.y += b.y; a.z += b.z; a.w += b.w;
            s_acc[threadIdx.x] = a;
        }
        __syncthreads();
    }
    if (threadIdx.x == 0) {
        float cden = fmaxf((float)(hi - lo), 1.0f);
        float v[CC];
        float mx = -1e30f;
#pragma unroll
        for (int s = 0; s < 4; s++) {
            float4 a = s_acc[s];
            v[s * 4 + 0] = a.x / cden; v[s * 4 + 1] = a.y / cden;
            v[s * 4 + 2] = a.z / cden; v[s * 4 + 3] = a.w / cden;
        }
#pragma unroll
        for (int j = 0; j < CC; j++) mx = fmaxf(mx, v[j]);
        float ssum = 0.f;
#pragma unroll
        for (int j = 0; j < CC; j++) { v[j] = __expf(v[j] - mx); ssum += v[j]; }
        float inv = 1.0f / ssum;
#pragma unroll
        for (int j = 0; j < CC; j++) out[g * CC + j] = v[j] * inv;
    }
}

// ---------------- launch ----------------
extern "C" void kernel_launch(void* const* d_in, const int* in_sizes, int n_in,
                              void* d_out, int out_size) {
    const float* x      = (const float*)d_in[0];
    const int*   ei     = (const int*)d_in[1];
    const int*   batch  = (const int*)d_in[2];
    const float* emb    = (const float*)d_in[3];
    const float* W1     = (const float*)d_in[4];
    const float* a1s    = (const float*)d_in[5];
    const float* a1d    = (const float*)d_in[6];
    const float* b1     = (const float*)d_in[7];
    const float* W2     = (const float*)d_in[8];
    const float* a2s    = (const float*)d_in[9];
    const float* a2d    = (const float*)d_in[10];
    const float* b2     = (const float*)d_in[11];
    float* out = (float*)d_out;

    const int node16Blocks = NN / 16;                 // 6250

    k_zero<<<ZEROB, 256>>>();
    k_fused<<<3 * AMXB + 1, 256>>>(x, ei, emb, W1, a1s, a1d);
    k_layer1<<<node16Blocks, 256>>>(b1, W2, a2s, a2d);
    k_layer2<<<node16Blocks, 256>>>(b2);
    k_final<<<GG, 256>>>(batch, out);
    (void)in_sizes; (void)n_in; (void)out_size;
}